// round 13
// baseline (speedup 1.0000x reference)
#include <cuda_runtime.h>
#include <cuda_bf16.h>
#include <math_constants.h>

// Problem constants (fixed by the reference)
#define NNODES 8192
#define NB     64
#define E0     32768
#define DIN1   32
#define DH     64
#define BOND   5
// P layout: [N][6][64]  (k=0..4 bond projections, k=5 bias projection)
#define PSTRIDE (6*DH)   // 384

// Scratch (allocation-free rule: __device__ globals)
__device__ float g_P[NNODES * PSTRIDE];   // 12.6 MB, reused for layer 1 and 2
__device__ float g_agg[NNODES * DH];      // 2 MB, reused for layer 1 and 2

// Packed f32x2 FMA (Blackwell): acc.{lo,hi} += a.{lo,hi} * b.{lo,hi}
__device__ __forceinline__ void ffma2(unsigned long long& acc,
                                      unsigned long long a,
                                      unsigned long long b) {
    asm("fma.rn.f32x2 %0, %1, %2, %0;" : "+l"(acc) : "l"(a), "l"(b));
}
__device__ __forceinline__ unsigned long long pack2(float a, float b) {
    unsigned long long r;
    asm("mov.b64 %0, {%1, %2};" : "=l"(r) : "f"(a), "f"(b));
    return r;
}
__device__ __forceinline__ float unpack_sum(unsigned long long v) {
    float lo, hi;
    asm("mov.b64 {%0, %1}, %2;" : "=f"(lo), "=f"(hi) : "l"(v));
    return lo + hi;
}

// ---------------------------------------------------------------------------
// Projection: P[n, k*64+o] = sum_i x[n,i] * W_k[i,o]
//   W_k[i,o] = eW[k, i*64+o] for k<5, eb[i*64+o] for k==5
// Also fuses agg init: agg[n,o] = bias[o] + P_5[n,o]  (self-loop msg + bias)
// blockDim = 384 (thread owns one (k,o) column), 8 nodes per group,
// grid-stride over 1024 groups. Even/odd input dims packed into f32x2 lanes.
// ---------------------------------------------------------------------------
template<int DIN, int RELU_IN>
__global__ void __launch_bounds__(384) proj_kernel(
    const float* __restrict__ x,     // [N, DIN]
    const float* __restrict__ eW,    // [5, DIN*64]
    const float* __restrict__ eb,    // [DIN*64]
    const float* __restrict__ bias,  // [64]
    float* __restrict__ P,           // [N, 384]
    float* __restrict__ agg)         // [N, 64]
{
    const int tid = threadIdx.x;
    const int k = tid >> 6;
    const int o = tid & 63;

    // pre-packed weight column: wp[c] = (w[2c], w[2c+1])
    unsigned long long wp[DIN / 2];
    const float* wsrc = (k < 5) ? (eW + k * DIN * 64) : eb;
    #pragma unroll
    for (int c = 0; c < DIN / 2; c++)
        wp[c] = pack2(wsrc[(2 * c) * 64 + o], wsrc[(2 * c + 1) * 64 + o]);

    const float bo = bias[o];

    // 8 node rows of DIN floats (plain row layout; reads are warp-broadcast)
    __shared__ ulonglong2 xs[8][DIN / 4];

    for (int g = blockIdx.x; g < NNODES / 8; g += gridDim.x) {
        const int nbase = g * 8;

        // cooperative vectorized load (nodes are contiguous in memory)
        const float4* xg = reinterpret_cast<const float4*>(x + (size_t)nbase * DIN);
        if (tid < 2 * DIN) {
            float4 v = xg[tid];
            if (RELU_IN) {
                v.x = fmaxf(v.x, 0.f); v.y = fmaxf(v.y, 0.f);
                v.z = fmaxf(v.z, 0.f); v.w = fmaxf(v.w, 0.f);
            }
            reinterpret_cast<float4*>(xs)[tid] = v;
        }
        __syncthreads();

        unsigned long long acc[8];
        #pragma unroll
        for (int j = 0; j < 8; j++) acc[j] = 0ull;  // (0.f, 0.f)

        #pragma unroll
        for (int c = 0; c < DIN / 4; c++) {
            #pragma unroll
            for (int j = 0; j < 8; j++) {
                ulonglong2 v = xs[j][c];           // LDS.128 broadcast
                ffma2(acc[j], wp[2 * c],     v.x); // dims 4c, 4c+1
                ffma2(acc[j], wp[2 * c + 1], v.y); // dims 4c+2, 4c+3
            }
        }
        __syncthreads();

        #pragma unroll
        for (int j = 0; j < 8; j++) {
            const float r = unpack_sum(acc[j]);
            P[(size_t)(nbase + j) * PSTRIDE + tid] = r;
            if (k == 5)  // warp-uniform branch: fused agg init (bias + self-loop)
                agg[(size_t)(nbase + j) * DH + o] = bo + r;
        }
    }
}

// ---------------------------------------------------------------------------
// Edge scatter: 2 edges per warp (16 lanes each); lane owns 4 channels.
//   m = P_b[src] + sum_k ef[e,k] * P_k[src]
//   reduction into agg[dst] via red.global.add.v4.f32 (one RED.128 per lane)
// ---------------------------------------------------------------------------
__global__ void __launch_bounds__(256) edge_kernel(
    const float* __restrict__ P,
    const float* __restrict__ ef,   // [E0, 5]
    const int*   __restrict__ src,
    const int*   __restrict__ dst,
    float* __restrict__ agg)
{
    const int warp = (blockIdx.x * blockDim.x + threadIdx.x) >> 5;
    const int lane = threadIdx.x & 31;
    const int e = warp * 2 + (lane >> 4);   // 2 edges per warp
    if (e >= E0) return;
    const int l = lane & 15;                // 16 lanes x float4 = 64 channels

    const int s = __ldg(src + e);
    const int d = __ldg(dst + e);
    const float f0 = __ldg(ef + e * BOND + 0);
    const float f1 = __ldg(ef + e * BOND + 1);
    const float f2 = __ldg(ef + e * BOND + 2);
    const float f3 = __ldg(ef + e * BOND + 3);
    const float f4 = __ldg(ef + e * BOND + 4);

    const float4* p = reinterpret_cast<const float4*>(P + (size_t)s * PSTRIDE);
    const float4 pb = __ldg(p + 5 * 16 + l);
    const float4 p0 = __ldg(p + 0 * 16 + l);
    const float4 p1 = __ldg(p + 1 * 16 + l);
    const float4 p2 = __ldg(p + 2 * 16 + l);
    const float4 p3 = __ldg(p + 3 * 16 + l);
    const float4 p4 = __ldg(p + 4 * 16 + l);

    float4 m;
    m.x = fmaf(f0, p0.x, pb.x); m.y = fmaf(f0, p0.y, pb.y);
    m.z = fmaf(f0, p0.z, pb.z); m.w = fmaf(f0, p0.w, pb.w);
    m.x = fmaf(f1, p1.x, m.x);  m.y = fmaf(f1, p1.y, m.y);
    m.z = fmaf(f1, p1.z, m.z);  m.w = fmaf(f1, p1.w, m.w);
    m.x = fmaf(f2, p2.x, m.x);  m.y = fmaf(f2, p2.y, m.y);
    m.z = fmaf(f2, p2.z, m.z);  m.w = fmaf(f2, p2.w, m.w);
    m.x = fmaf(f3, p3.x, m.x);  m.y = fmaf(f3, p3.y, m.y);
    m.z = fmaf(f3, p3.z, m.z);  m.w = fmaf(f3, p3.w, m.w);
    m.x = fmaf(f4, p4.x, m.x);  m.y = fmaf(f4, p4.y, m.y);
    m.z = fmaf(f4, p4.z, m.z);  m.w = fmaf(f4, p4.w, m.w);

    float* a = agg + (size_t)d * DH + 4 * l;   // 16B-aligned
    asm volatile("red.global.add.v4.f32 [%0], {%1, %2, %3, %4};"
                 :: "l"(a), "f"(m.x), "f"(m.y), "f"(m.z), "f"(m.w)
                 : "memory");
}

// ---------------------------------------------------------------------------
// Pooling + timestep conditioning + final activation
// one block per graph (128 contiguous nodes), 128 threads
// ---------------------------------------------------------------------------
__global__ void __launch_bounds__(128) pool_kernel(
    const float* __restrict__ agg,   // [N, 64] (pre-relu)
    const float* __restrict__ wsW,   // [64]
    const float* __restrict__ wsb,   // [1]
    const float* __restrict__ tstep, // [B]
    float* __restrict__ out)         // [B, 128]
{
    __shared__ float hs[128][65];
    __shared__ float wv[128];
    __shared__ float gsum[64];
    __shared__ float gmax[64];

    const int g = blockIdx.x;
    const int t = threadIdx.x;
    const int base = g * 128;

    // coalesced load + relu
    for (int idx = t; idx < 128 * 64; idx += 128) {
        hs[idx >> 6][idx & 63] = fmaxf(agg[base * 64 + idx], 0.0f);
    }
    __syncthreads();

    // node weight w = sigmoid(h @ wsW + wsb)
    float acc = 0.f;
    #pragma unroll
    for (int c = 0; c < 64; c++) acc = fmaf(hs[t][c], wsW[c], acc);
    wv[t] = 1.0f / (1.0f + expf(-(acc + wsb[0])));
    __syncthreads();

    if (t < 64) {
        float s = 0.f, m = -CUDART_INF_F;
        #pragma unroll 4
        for (int r = 0; r < 128; r++) {
            const float h = hs[r][t];
            s = fmaf(h, wv[r], s);
            m = fmaxf(m, h);
        }
        gsum[t] = s;
        gmax[t] = m;
    }
    __syncthreads();

    const float ts = tstep[g];
    float v;
    if (t < 64) {
        const float inv = expf(-logf(10000.0f) * (2.0f * t) / 128.0f);
        v = gsum[t] + sinf(ts * inv);
    } else {
        const int j = t - 64;
        const float inv = expf(-logf(10000.0f) * (2.0f * j) / 128.0f);
        v = gmax[j] + cosf(ts * inv);
    }
    out[g * 128 + t] = tanhf(fmaxf(v, 0.0f));
}

// ---------------------------------------------------------------------------
extern "C" void kernel_launch(void* const* d_in, const int* in_sizes, int n_in,
                              void* d_out, int out_size)
{
    const float* node_feats = (const float*)d_in[0];   // [8192, 32]
    const float* edge_feats = (const float*)d_in[1];   // [32768, 5]
    const int*   src        = (const int*)  d_in[2];   // [32768]
    const int*   dst        = (const int*)  d_in[3];   // [32768]
    // d_in[4] = graph_ids (contiguous: g = n/128), unused
    const float* timestep   = (const float*)d_in[5];   // [64, 1]
    const float* edge_W1    = (const float*)d_in[6];   // [5, 2048]
    const float* edge_b1    = (const float*)d_in[7];   // [2048]
    const float* bias1      = (const float*)d_in[8];   // [64]
    const float* edge_W2    = (const float*)d_in[9];   // [5, 4096]
    const float* edge_b2    = (const float*)d_in[10];  // [4096]
    const float* bias2      = (const float*)d_in[11];  // [64]
    const float* ws_W       = (const float*)d_in[12];  // [64]
    const float* ws_b       = (const float*)d_in[13];  // [1]
    float* out = (float*)d_out;                        // [64, 128]

    float* P   = nullptr;
    float* agg = nullptr;
    cudaGetSymbolAddress((void**)&P,   g_P);
    cudaGetSymbolAddress((void**)&agg, g_agg);

    // 2 edges per warp, 8 warps per block -> 16 edges/block
    const int edge_blocks = E0 / 16;                   // 2048

    // Layer 1 (proj also initializes agg = bias1 + self-loop message)
    proj_kernel<DIN1, 0><<<296, 384>>>(node_feats, edge_W1, edge_b1, bias1, P, agg);
    edge_kernel<<<edge_blocks, 256>>>(P, edge_feats, src, dst, agg);

    // Layer 2 (relu applied to layer-1 agg on load)
    proj_kernel<DH, 1><<<148, 384>>>(agg, edge_W2, edge_b2, bias2, P, agg);
    edge_kernel<<<edge_blocks, 256>>>(P, edge_feats, src, dst, agg);

    // Pool + timestep + tanh(relu(.))
    pool_kernel<<<NB, 128>>>(agg, ws_W, ws_b, timestep, out);
}

// round 15
// speedup vs baseline: 1.0061x; 1.0061x over previous
#include <cuda_runtime.h>
#include <cuda_bf16.h>
#include <math_constants.h>

// Problem constants (fixed by the reference)
#define NNODES 8192
#define NB     64
#define E0     32768
#define DIN1   32
#define DH     64
#define BOND   5
// P layout: [N][6][64]  (k=0..4 bond projections, k=5 bias projection)
#define PSTRIDE (6*DH)   // 384

// Scratch (allocation-free rule: __device__ globals)
__device__ float g_P[NNODES * PSTRIDE];   // 12.6 MB, reused for layer 1 and 2
__device__ float g_agg[NNODES * DH];      // 2 MB, reused for layer 1 and 2

// Packed f32x2 FMA (Blackwell): acc.{lo,hi} += a.{lo,hi} * b.{lo,hi}
__device__ __forceinline__ void ffma2(unsigned long long& acc,
                                      unsigned long long a,
                                      unsigned long long b) {
    asm("fma.rn.f32x2 %0, %1, %2, %0;" : "+l"(acc) : "l"(a), "l"(b));
}
__device__ __forceinline__ unsigned long long pack2(float a, float b) {
    unsigned long long r;
    asm("mov.b64 %0, {%1, %2};" : "=l"(r) : "f"(a), "f"(b));
    return r;
}
__device__ __forceinline__ float unpack_sum(unsigned long long v) {
    float lo, hi;
    asm("mov.b64 {%0, %1}, %2;" : "=f"(lo), "=f"(hi) : "l"(v));
    return lo + hi;
}

// ---------------------------------------------------------------------------
// Projection: P[n, k*64+o] = sum_i x[n,i] * W_k[i,o]
//   W_k[i,o] = eW[k, i*64+o] for k<5, eb[i*64+o] for k==5
// Also fuses agg init: agg[n,o] = bias[o] + P_5[n,o]  (self-loop msg + bias)
// blockDim = 384 (thread owns one (k,o) column), 8 nodes per group,
// grid-stride over 1024 groups. Even/odd input dims packed into f32x2 lanes.
// ---------------------------------------------------------------------------
template<int DIN, int RELU_IN>
__global__ void __launch_bounds__(384) proj_kernel(
    const float* __restrict__ x,     // [N, DIN]
    const float* __restrict__ eW,    // [5, DIN*64]
    const float* __restrict__ eb,    // [DIN*64]
    const float* __restrict__ bias,  // [64]
    float* __restrict__ P,           // [N, 384]
    float* __restrict__ agg)         // [N, 64]
{
    const int tid = threadIdx.x;
    const int k = tid >> 6;
    const int o = tid & 63;

    // pre-packed weight column: wp[c] = (w[2c], w[2c+1])
    unsigned long long wp[DIN / 2];
    const float* wsrc = (k < 5) ? (eW + k * DIN * 64) : eb;
    #pragma unroll
    for (int c = 0; c < DIN / 2; c++)
        wp[c] = pack2(wsrc[(2 * c) * 64 + o], wsrc[(2 * c + 1) * 64 + o]);

    const float bo = bias[o];

    // 8 node rows of DIN floats (plain row layout; reads are warp-broadcast)
    __shared__ ulonglong2 xs[8][DIN / 4];

    for (int g = blockIdx.x; g < NNODES / 8; g += gridDim.x) {
        const int nbase = g * 8;

        // cooperative vectorized load (nodes are contiguous in memory)
        const float4* xg = reinterpret_cast<const float4*>(x + (size_t)nbase * DIN);
        if (tid < 2 * DIN) {
            float4 v = xg[tid];
            if (RELU_IN) {
                v.x = fmaxf(v.x, 0.f); v.y = fmaxf(v.y, 0.f);
                v.z = fmaxf(v.z, 0.f); v.w = fmaxf(v.w, 0.f);
            }
            reinterpret_cast<float4*>(xs)[tid] = v;
        }
        __syncthreads();

        unsigned long long acc[8];
        #pragma unroll
        for (int j = 0; j < 8; j++) acc[j] = 0ull;  // (0.f, 0.f)

        #pragma unroll
        for (int c = 0; c < DIN / 4; c++) {
            #pragma unroll
            for (int j = 0; j < 8; j++) {
                ulonglong2 v = xs[j][c];           // LDS.128 broadcast
                ffma2(acc[j], wp[2 * c],     v.x); // dims 4c, 4c+1
                ffma2(acc[j], wp[2 * c + 1], v.y); // dims 4c+2, 4c+3
            }
        }
        __syncthreads();

        #pragma unroll
        for (int j = 0; j < 8; j++) {
            const float r = unpack_sum(acc[j]);
            P[(size_t)(nbase + j) * PSTRIDE + tid] = r;
            if (k == 5)  // warp-uniform branch: fused agg init (bias + self-loop)
                agg[(size_t)(nbase + j) * DH + o] = bo + r;
        }
    }
}

// ---------------------------------------------------------------------------
// Edge scatter: 2 edges per warp (16 lanes each); lane owns 4 channels.
//   m = P_b[src] + sum_k ef[e,k] * P_k[src]
//   reduction into agg[dst] via red.global.add.v4.f32 (one RED.128 per lane)
// ---------------------------------------------------------------------------
__global__ void __launch_bounds__(256) edge_kernel(
    const float* __restrict__ P,
    const float* __restrict__ ef,   // [E0, 5]
    const int*   __restrict__ src,
    const int*   __restrict__ dst,
    float* __restrict__ agg)
{
    const int warp = (blockIdx.x * blockDim.x + threadIdx.x) >> 5;
    const int lane = threadIdx.x & 31;
    const int e = warp * 2 + (lane >> 4);   // 2 edges per warp
    if (e >= E0) return;
    const int l = lane & 15;                // 16 lanes x float4 = 64 channels

    const int s = __ldg(src + e);
    const int d = __ldg(dst + e);
    const float f0 = __ldg(ef + e * BOND + 0);
    const float f1 = __ldg(ef + e * BOND + 1);
    const float f2 = __ldg(ef + e * BOND + 2);
    const float f3 = __ldg(ef + e * BOND + 3);
    const float f4 = __ldg(ef + e * BOND + 4);

    const float4* p = reinterpret_cast<const float4*>(P + (size_t)s * PSTRIDE);
    const float4 pb = __ldg(p + 5 * 16 + l);
    const float4 p0 = __ldg(p + 0 * 16 + l);
    const float4 p1 = __ldg(p + 1 * 16 + l);
    const float4 p2 = __ldg(p + 2 * 16 + l);
    const float4 p3 = __ldg(p + 3 * 16 + l);
    const float4 p4 = __ldg(p + 4 * 16 + l);

    float4 m;
    m.x = fmaf(f0, p0.x, pb.x); m.y = fmaf(f0, p0.y, pb.y);
    m.z = fmaf(f0, p0.z, pb.z); m.w = fmaf(f0, p0.w, pb.w);
    m.x = fmaf(f1, p1.x, m.x);  m.y = fmaf(f1, p1.y, m.y);
    m.z = fmaf(f1, p1.z, m.z);  m.w = fmaf(f1, p1.w, m.w);
    m.x = fmaf(f2, p2.x, m.x);  m.y = fmaf(f2, p2.y, m.y);
    m.z = fmaf(f2, p2.z, m.z);  m.w = fmaf(f2, p2.w, m.w);
    m.x = fmaf(f3, p3.x, m.x);  m.y = fmaf(f3, p3.y, m.y);
    m.z = fmaf(f3, p3.z, m.z);  m.w = fmaf(f3, p3.w, m.w);
    m.x = fmaf(f4, p4.x, m.x);  m.y = fmaf(f4, p4.y, m.y);
    m.z = fmaf(f4, p4.z, m.z);  m.w = fmaf(f4, p4.w, m.w);

    float* a = agg + (size_t)d * DH + 4 * l;   // 16B-aligned
    asm volatile("red.global.add.v4.f32 [%0], {%1, %2, %3, %4};"
                 :: "l"(a), "f"(m.x), "f"(m.y), "f"(m.z), "f"(m.w)
                 : "memory");
}

// ---------------------------------------------------------------------------
// Pooling + timestep conditioning + final activation
// one block per graph (128 contiguous nodes), 128 threads
// ---------------------------------------------------------------------------
__global__ void __launch_bounds__(128) pool_kernel(
    const float* __restrict__ agg,   // [N, 64] (pre-relu)
    const float* __restrict__ wsW,   // [64]
    const float* __restrict__ wsb,   // [1]
    const float* __restrict__ tstep, // [B]
    float* __restrict__ out)         // [B, 128]
{
    __shared__ float hs[128][65];
    __shared__ float wv[128];
    __shared__ float gsum[64];
    __shared__ float gmax[64];

    const int g = blockIdx.x;
    const int t = threadIdx.x;
    const int base = g * 128;

    // coalesced load + relu
    for (int idx = t; idx < 128 * 64; idx += 128) {
        hs[idx >> 6][idx & 63] = fmaxf(agg[base * 64 + idx], 0.0f);
    }
    __syncthreads();

    // node weight w = sigmoid(h @ wsW + wsb)
    float acc = 0.f;
    #pragma unroll
    for (int c = 0; c < 64; c++) acc = fmaf(hs[t][c], wsW[c], acc);
    wv[t] = 1.0f / (1.0f + expf(-(acc + wsb[0])));
    __syncthreads();

    if (t < 64) {
        float s = 0.f, m = -CUDART_INF_F;
        #pragma unroll 4
        for (int r = 0; r < 128; r++) {
            const float h = hs[r][t];
            s = fmaf(h, wv[r], s);
            m = fmaxf(m, h);
        }
        gsum[t] = s;
        gmax[t] = m;
    }
    __syncthreads();

    const float ts = tstep[g];
    float v;
    if (t < 64) {
        const float inv = expf(-logf(10000.0f) * (2.0f * t) / 128.0f);
        v = gsum[t] + sinf(ts * inv);
    } else {
        const int j = t - 64;
        const float inv = expf(-logf(10000.0f) * (2.0f * j) / 128.0f);
        v = gmax[j] + cosf(ts * inv);
    }
    out[g * 128 + t] = tanhf(fmaxf(v, 0.0f));
}

// ---------------------------------------------------------------------------
extern "C" void kernel_launch(void* const* d_in, const int* in_sizes, int n_in,
                              void* d_out, int out_size)
{
    const float* node_feats = (const float*)d_in[0];   // [8192, 32]
    const float* edge_feats = (const float*)d_in[1];   // [32768, 5]
    const int*   src        = (const int*)  d_in[2];   // [32768]
    const int*   dst        = (const int*)  d_in[3];   // [32768]
    // d_in[4] = graph_ids (contiguous: g = n/128), unused
    const float* timestep   = (const float*)d_in[5];   // [64, 1]
    const float* edge_W1    = (const float*)d_in[6];   // [5, 2048]
    const float* edge_b1    = (const float*)d_in[7];   // [2048]
    const float* bias1      = (const float*)d_in[8];   // [64]
    const float* edge_W2    = (const float*)d_in[9];   // [5, 4096]
    const float* edge_b2    = (const float*)d_in[10];  // [4096]
    const float* bias2      = (const float*)d_in[11];  // [64]
    const float* ws_W       = (const float*)d_in[12];  // [64]
    const float* ws_b       = (const float*)d_in[13];  // [1]
    float* out = (float*)d_out;                        // [64, 128]

    float* P   = nullptr;
    float* agg = nullptr;
    cudaGetSymbolAddress((void**)&P,   g_P);
    cudaGetSymbolAddress((void**)&agg, g_agg);

    // 2 edges per warp, 8 warps per block -> 16 edges/block
    const int edge_blocks = E0 / 16;                   // 2048

    // Layer 1 (proj also initializes agg = bias1 + self-loop message)
    proj_kernel<DIN1, 0><<<296, 384>>>(node_feats, edge_W1, edge_b1, bias1, P, agg);
    edge_kernel<<<edge_blocks, 256>>>(P, edge_feats, src, dst, agg);

    // Layer 2 (relu applied to layer-1 agg on load)
    proj_kernel<DH, 1><<<148, 384>>>(agg, edge_W2, edge_b2, bias2, P, agg);
    edge_kernel<<<edge_blocks, 256>>>(P, edge_feats, src, dst, agg);

    // Pool + timestep + tanh(relu(.))
    pool_kernel<<<NB, 128>>>(agg, ws_W, ws_b, timestep, out);
}